// round 1
// baseline (speedup 1.0000x reference)
#include <cuda_runtime.h>
#include <math.h>

#define N_NODES 50000
#define N_EDGES 800000
#define H 128
#define LN_EPS 1e-5f

// Scratch: per-node projections. Layout [node][256]: cols 0..127 = P = x@Ws + b1,
// cols 128..255 = Q = x@Wr.  51.2 MB static device allocation (allowed).
__device__ float g_PQ[(size_t)N_NODES * 256];

// ---------------------------------------------------------------------------
// Kernel 1: node projection.  GEMM  [N_NODES x 128] @ [128 x 128] twice
// (blockIdx.y = 0 -> Ws (rows 0..127 of W1, +b1), 1 -> Wr (rows 128..255)).
// 64 rows/block, 256 threads, per-thread 8x4 register tile.
// ---------------------------------------------------------------------------
__global__ __launch_bounds__(256) void proj_kernel(const float* __restrict__ x,
                                                   const float* __restrict__ W1,
                                                   const float* __restrict__ b1) {
    __shared__ float As[128 * 64];   // As[k][m]  (transposed)
    __shared__ float Bs[32 * 128];   // Bs[k][o]  (staged 32-k chunk)

    const int tid  = threadIdx.x;
    const int half = blockIdx.y;            // 0 = P(Ws)+b1, 1 = Q(Wr)
    const int m0   = blockIdx.x * 64;
    const int eg   = tid >> 5;              // row group 0..7  (8 rows each)
    const int og   = tid & 31;              // col group 0..31 (4 cols each)

    // Load A tile transposed into SMEM (guard tail rows with zeros)
#pragma unroll
    for (int it = 0; it < 8; ++it) {
        int idx = tid + it * 256;
        int m   = idx & 63;
        int kg  = idx >> 6;                 // 0..31 -> k = 4*kg
        int n   = m0 + m;
        float4 v = make_float4(0.f, 0.f, 0.f, 0.f);
        if (n < N_NODES) v = *(const float4*)(x + (size_t)n * H + kg * 4);
        As[(kg * 4 + 0) * 64 + m] = v.x;
        As[(kg * 4 + 1) * 64 + m] = v.y;
        As[(kg * 4 + 2) * 64 + m] = v.z;
        As[(kg * 4 + 3) * 64 + m] = v.w;
    }

    float4 acc[8];
#pragma unroll
    for (int i = 0; i < 8; ++i) acc[i] = make_float4(0.f, 0.f, 0.f, 0.f);

    const float* B = W1 + (size_t)half * 128 * H;

    for (int kc = 0; kc < 4; ++kc) {
        __syncthreads();
        // stage 32 rows of B
#pragma unroll
        for (int it = 0; it < 4; ++it) {
            int idx = tid + it * 256;
            int o4  = idx & 31;
            int r   = idx >> 5;
            *(float4*)(Bs + r * 128 + o4 * 4) =
                *(const float4*)(B + (size_t)(kc * 32 + r) * H + o4 * 4);
        }
        __syncthreads();
#pragma unroll
        for (int k = 0; k < 32; ++k) {
            const float* ap = As + (kc * 32 + k) * 64 + eg * 8;
            float4 a0 = *(const float4*)(ap);
            float4 a1 = *(const float4*)(ap + 4);
            float4 b  = *(const float4*)(Bs + k * 128 + og * 4);
            float ar[8] = {a0.x, a0.y, a0.z, a0.w, a1.x, a1.y, a1.z, a1.w};
#pragma unroll
            for (int i = 0; i < 8; ++i) {
                acc[i].x += ar[i] * b.x;
                acc[i].y += ar[i] * b.y;
                acc[i].z += ar[i] * b.z;
                acc[i].w += ar[i] * b.w;
            }
        }
    }

    float4 bias = make_float4(0.f, 0.f, 0.f, 0.f);
    if (half == 0) bias = *(const float4*)(b1 + og * 4);

#pragma unroll
    for (int i = 0; i < 8; ++i) {
        int n = m0 + eg * 8 + i;
        if (n < N_NODES) {
            float4 v;
            v.x = acc[i].x + bias.x;
            v.y = acc[i].y + bias.y;
            v.z = acc[i].z + bias.z;
            v.w = acc[i].w + bias.w;
            *(float4*)(g_PQ + (size_t)n * 256 + half * 128 + og * 4) = v;
        }
    }
}

// ---------------------------------------------------------------------------
// Kernel 2: out = x  (residual preload; atomics then accumulate into out)
// ---------------------------------------------------------------------------
__global__ void init_kernel(float* __restrict__ out, const float* __restrict__ x) {
    int i = blockIdx.x * blockDim.x + threadIdx.x;
    if (i < N_NODES * H / 4) ((float4*)out)[i] = ((const float4*)x)[i];
}

// ---------------------------------------------------------------------------
// Kernel 3: edge GEMM  ef[64x128] @ We[128x128] per block, epilogue gathers
// P[s], Q[r], relu, atomicAdd into out[r].
// ---------------------------------------------------------------------------
__global__ __launch_bounds__(256) void edge_kernel(const float* __restrict__ ef,
                                                   const int* __restrict__ senders,
                                                   const int* __restrict__ receivers,
                                                   const float* __restrict__ W1,
                                                   float* __restrict__ out) {
    __shared__ float As[128 * 64];   // As[k][e]
    __shared__ float Bs[32 * 128];   // Bs[k][o]

    const int tid = threadIdx.x;
    const int e0  = blockIdx.x * 64;
    const int eg  = tid >> 5;
    const int og  = tid & 31;

#pragma unroll
    for (int it = 0; it < 8; ++it) {
        int idx = tid + it * 256;
        int e   = idx & 63;
        int kg  = idx >> 6;
        float4 v = *(const float4*)(ef + (size_t)(e0 + e) * H + kg * 4);
        As[(kg * 4 + 0) * 64 + e] = v.x;
        As[(kg * 4 + 1) * 64 + e] = v.y;
        As[(kg * 4 + 2) * 64 + e] = v.z;
        As[(kg * 4 + 3) * 64 + e] = v.w;
    }

    float4 acc[8];
#pragma unroll
    for (int i = 0; i < 8; ++i) acc[i] = make_float4(0.f, 0.f, 0.f, 0.f);

    const float* B = W1 + (size_t)256 * H;   // We = rows 256..383 of W1

    for (int kc = 0; kc < 4; ++kc) {
        __syncthreads();
#pragma unroll
        for (int it = 0; it < 4; ++it) {
            int idx = tid + it * 256;
            int o4  = idx & 31;
            int r   = idx >> 5;
            *(float4*)(Bs + r * 128 + o4 * 4) =
                *(const float4*)(B + (size_t)(kc * 32 + r) * H + o4 * 4);
        }
        __syncthreads();
#pragma unroll
        for (int k = 0; k < 32; ++k) {
            const float* ap = As + (kc * 32 + k) * 64 + eg * 8;
            float4 a0 = *(const float4*)(ap);
            float4 a1 = *(const float4*)(ap + 4);
            float4 b  = *(const float4*)(Bs + k * 128 + og * 4);
            float ar[8] = {a0.x, a0.y, a0.z, a0.w, a1.x, a1.y, a1.z, a1.w};
#pragma unroll
            for (int i = 0; i < 8; ++i) {
                acc[i].x += ar[i] * b.x;
                acc[i].y += ar[i] * b.y;
                acc[i].z += ar[i] * b.z;
                acc[i].w += ar[i] * b.w;
            }
        }
    }

    // Epilogue: msg = relu(acc + P[s] + Q[r]) ; atomic scatter to out[r]
#pragma unroll
    for (int i = 0; i < 8; ++i) {
        int e = e0 + eg * 8 + i;
        int s = senders[e];
        int r = receivers[e];
        const float4 p = *(const float4*)(g_PQ + (size_t)s * 256 + og * 4);
        const float4 q = *(const float4*)(g_PQ + (size_t)r * 256 + 128 + og * 4);
        float4 m;
        m.x = fmaxf(acc[i].x + p.x + q.x, 0.f);
        m.y = fmaxf(acc[i].y + p.y + q.y, 0.f);
        m.z = fmaxf(acc[i].z + p.z + q.z, 0.f);
        m.w = fmaxf(acc[i].w + p.w + q.w, 0.f);
        float* dst = out + (size_t)r * H + og * 4;
        atomicAdd(dst + 0, m.x);
        atomicAdd(dst + 1, m.y);
        atomicAdd(dst + 2, m.z);
        atomicAdd(dst + 3, m.w);
    }
}

// ---------------------------------------------------------------------------
// Kernel 4: in-place LayerNorm, one warp per row (8 rows / 256-thread block)
// ---------------------------------------------------------------------------
__global__ __launch_bounds__(256) void ln_kernel(float* __restrict__ out,
                                                 const float* __restrict__ gamma,
                                                 const float* __restrict__ beta) {
    int warp = threadIdx.x >> 5;
    int lane = threadIdx.x & 31;
    int row  = blockIdx.x * 8 + warp;
    if (row >= N_NODES) return;

    float4 h = *(const float4*)(out + (size_t)row * H + lane * 4);
    float s  = h.x + h.y + h.z + h.w;
    float s2 = h.x * h.x + h.y * h.y + h.z * h.z + h.w * h.w;
#pragma unroll
    for (int off = 16; off > 0; off >>= 1) {
        s  += __shfl_xor_sync(0xffffffffu, s, off);
        s2 += __shfl_xor_sync(0xffffffffu, s2, off);
    }
    float mean = s * (1.f / H);
    float var  = s2 * (1.f / H) - mean * mean;
    float rstd = rsqrtf(var + LN_EPS);

    float4 g = *(const float4*)(gamma + lane * 4);
    float4 b = *(const float4*)(beta + lane * 4);
    float4 o;
    o.x = g.x * (h.x - mean) * rstd + b.x;
    o.y = g.y * (h.y - mean) * rstd + b.y;
    o.z = g.z * (h.z - mean) * rstd + b.z;
    o.w = g.w * (h.w - mean) * rstd + b.w;
    *(float4*)(out + (size_t)row * H + lane * 4) = o;
}

// ---------------------------------------------------------------------------
extern "C" void kernel_launch(void* const* d_in, const int* in_sizes, int n_in,
                              void* d_out, int out_size) {
    const float* x         = (const float*)d_in[0];
    const int*   senders   = (const int*)d_in[1];
    const int*   receivers = (const int*)d_in[2];
    const float* ef        = (const float*)d_in[3];
    const float* W1        = (const float*)d_in[4];
    const float* b1        = (const float*)d_in[5];
    const float* gamma     = (const float*)d_in[6];
    const float* beta      = (const float*)d_in[7];
    float*       out       = (float*)d_out;

    proj_kernel<<<dim3((N_NODES + 63) / 64, 2), 256>>>(x, W1, b1);
    init_kernel<<<(N_NODES * H / 4 + 255) / 256, 256>>>(out, x);
    edge_kernel<<<N_EDGES / 64, 256>>>(ef, senders, receivers, W1, out);
    ln_kernel<<<N_NODES / 8, 256>>>(out, gamma, beta);
}